// round 5
// baseline (speedup 1.0000x reference)
#include <cuda_runtime.h>

// SpatialShift: x (ns=128, m=12, t=784, c=64) fp32.
// ns = b*16 + h*4 + w (H=W=4, shift s=1). Channel d = m*64 + c, fold f=48.
// Pure ns-index permutation => fully coalesced float4 streaming copy.
//
// R5: R2/R4 shape (7 loads front-batched = max bytes-in-flight) but with
// __launch_bounds__(256, 7) forcing regs <= 36 so 7 CTAs/SM fit
// (bytes-in-flight 172KB -> 201KB per SM).

// Packed delta tables: 2 bits per group g (0..8), value = delta + 1.
// dh: {+1,-1,0,0,-1,+1,-1,+1, 0}
// dw: { 0, 0,+1,-1,-1,+1,+1,-1, 0}
#define DH_PACK 100434u
#define DW_PACK 75813u

__global__ void __launch_bounds__(256, 7)
spatial_shift_kernel(const float4* __restrict__ x, float4* __restrict__ out) {
    const int c4      = threadIdx.x & 15;   // float4 index within c (0..15)
    const int t_local = threadIdx.x >> 4;   // 0..15

    int blk = blockIdx.x;
    const int tchunk = blk % 7;   blk /= 7;    // 7 * 112 = 784 = t
    const int m      = blk % 12;  blk /= 12;
    const int ns     = blk;                    // 0..127

    const int h = (ns >> 2) & 3;
    const int w = ns & 3;

    const int d = m * 64 + c4 * 4;
    int g = d / 48;
    if (g > 8) g = 8;

    const int dh = (int)((DH_PACK >> (2 * g)) & 3u) - 1;
    const int dw = (int)((DW_PACK >> (2 * g)) & 3u) - 1;

    int hs = h + dh;
    int ws = w + dw;
    bool zero = false;
    if (((unsigned)hs > 3u) || ((unsigned)ws > 3u)) {
        if (g < 4) {
            zero = true;            // axis shifts: out-of-bounds -> 0
        } else {
            hs = h; ws = w;         // diagonal shifts: border -> identity
        }
    }

    const int t0 = tchunk * 112 + t_local;
    // float4 index of (ns, m, t, c4): ((ns*12 + m)*784 + t)*16 + c4
    // max = 128*12*784*16 = 19,267,584 < 2^31  -> 32-bit offsets are safe.
    const int base_out = ((ns * 12 + m) * 784 + t0) * 16 + c4;

    float4 v[7];
#pragma unroll
    for (int i = 0; i < 7; i++) v[i] = make_float4(0.f, 0.f, 0.f, 0.f);

    if (!zero) {
        const int ns_src   = (ns & ~15) | (hs << 2) | ws;
        const int base_src = ((ns_src * 12 + m) * 784 + t0) * 16 + c4;
#pragma unroll
        for (int i = 0; i < 7; i++)
            v[i] = __ldcs(x + base_src + i * 256);   // +16 t each = 256 float4
    }

#pragma unroll
    for (int i = 0; i < 7; i++)
        __stcs(out + base_out + i * 256, v[i]);
}

extern "C" void kernel_launch(void* const* d_in, const int* in_sizes, int n_in,
                              void* d_out, int out_size) {
    const float4* x = (const float4*)d_in[0];
    float4* out = (float4*)d_out;
    // blocks = 128 * 12 * 7 = 10,752 ; each moves 256 threads * 7 float4
    spatial_shift_kernel<<<10752, 256>>>(x, out);
}

// round 6
// speedup vs baseline: 1.0063x; 1.0063x over previous
#include <cuda_runtime.h>

// SpatialShift: x (ns=128, m=12, t=784, c=64) fp32.
// ns = b*16 + h*4 + w (H=W=4, shift s=1). Channel d = m*64 + c, fold f=48.
// Pure ns-index permutation => fully coalesced float4 streaming copy.
//
// R6: R4 shape (7 loads front-batched, no occupancy bound — forcing regs
// down causes spills, see R5), with grid reordered ns-fastest so all 128
// spatial cells are concurrently resident for the same t-window; duplicated
// diagonal-border reads then hit L2 instead of DRAM.

// Packed delta tables: 2 bits per group g (0..8), value = delta + 1.
// dh: {+1,-1,0,0,-1,+1,-1,+1, 0}
// dw: { 0, 0,+1,-1,-1,+1,+1,-1, 0}
#define DH_PACK 100434u
#define DW_PACK 75813u

__global__ void __launch_bounds__(256)
spatial_shift_kernel(const float4* __restrict__ x, float4* __restrict__ out) {
    const int c4      = threadIdx.x & 15;   // float4 index within c (0..15)
    const int t_local = threadIdx.x >> 4;   // 0..15

    // ns fastest, then m, then tchunk: concurrent CTAs cover all spatial
    // cells of the same (m, t-window) -> duplicate border reads hit L2.
    int blk = blockIdx.x;
    const int ns     = blk & 127;  blk >>= 7;  // 0..127
    const int m      = blk % 12;   blk /= 12;
    const int tchunk = blk;                    // 0..6  (7 * 112 = 784 = t)

    const int h = (ns >> 2) & 3;
    const int w = ns & 3;

    const int d = m * 64 + c4 * 4;
    int g = d / 48;
    if (g > 8) g = 8;

    const int dh = (int)((DH_PACK >> (2 * g)) & 3u) - 1;
    const int dw = (int)((DW_PACK >> (2 * g)) & 3u) - 1;

    int hs = h + dh;
    int ws = w + dw;
    bool zero = false;
    if (((unsigned)hs > 3u) || ((unsigned)ws > 3u)) {
        if (g < 4) {
            zero = true;            // axis shifts: out-of-bounds -> 0
        } else {
            hs = h; ws = w;         // diagonal shifts: border -> identity
        }
    }

    const int t0 = tchunk * 112 + t_local;
    // float4 index of (ns, m, t, c4): ((ns*12 + m)*784 + t)*16 + c4
    // max = 128*12*784*16 = 19,267,584 < 2^31  -> 32-bit offsets are safe.
    const int base_out = ((ns * 12 + m) * 784 + t0) * 16 + c4;

    float4 v[7];
#pragma unroll
    for (int i = 0; i < 7; i++) v[i] = make_float4(0.f, 0.f, 0.f, 0.f);

    if (!zero) {
        const int ns_src   = (ns & ~15) | (hs << 2) | ws;
        const int base_src = ((ns_src * 12 + m) * 784 + t0) * 16 + c4;
#pragma unroll
        for (int i = 0; i < 7; i++)
            v[i] = __ldcs(x + base_src + i * 256);   // +16 t each = 256 float4
    }

#pragma unroll
    for (int i = 0; i < 7; i++)
        __stcs(out + base_out + i * 256, v[i]);
}

extern "C" void kernel_launch(void* const* d_in, const int* in_sizes, int n_in,
                              void* d_out, int out_size) {
    const float4* x = (const float4*)d_in[0];
    float4* out = (float4*)d_out;
    // blocks = 7 * 12 * 128 = 10,752 ; each moves 256 threads * 7 float4
    spatial_shift_kernel<<<10752, 256>>>(x, out);
}

// round 7
// speedup vs baseline: 1.0194x; 1.0130x over previous
#include <cuda_runtime.h>

// SpatialShift: x (ns=128, m=12, t=784, c=64) fp32.
// ns = b*16 + h*4 + w (H=W=4, shift s=1). Channel d = m*64 + c, fold f=48.
// Pure ns-index permutation => fully coalesced float4 streaming copy.
//
// R7: R4's proven shape (7 loads front-batched, tchunk-fastest grid, no
// occupancy bound) but loads use DEFAULT caching (__ldg) instead of __ldcs:
// duplicated diagonal-border reads (~33MB) then hit L2 on second touch
// instead of being forced back to DRAM by the evict-first hint. Stores
// remain streaming (__stcs).

// Packed delta tables: 2 bits per group g (0..8), value = delta + 1.
// dh: {+1,-1,0,0,-1,+1,-1,+1, 0}
// dw: { 0, 0,+1,-1,-1,+1,+1,-1, 0}
#define DH_PACK 100434u
#define DW_PACK 75813u

__global__ void __launch_bounds__(256)
spatial_shift_kernel(const float4* __restrict__ x, float4* __restrict__ out) {
    const int c4      = threadIdx.x & 15;   // float4 index within c (0..15)
    const int t_local = threadIdx.x >> 4;   // 0..15

    int blk = blockIdx.x;
    const int tchunk = blk % 7;   blk /= 7;    // 7 * 112 = 784 = t
    const int m      = blk % 12;  blk /= 12;
    const int ns     = blk;                    // 0..127

    const int h = (ns >> 2) & 3;
    const int w = ns & 3;

    const int d = m * 64 + c4 * 4;
    int g = d / 48;
    if (g > 8) g = 8;

    const int dh = (int)((DH_PACK >> (2 * g)) & 3u) - 1;
    const int dw = (int)((DW_PACK >> (2 * g)) & 3u) - 1;

    int hs = h + dh;
    int ws = w + dw;
    bool zero = false;
    if (((unsigned)hs > 3u) || ((unsigned)ws > 3u)) {
        if (g < 4) {
            zero = true;            // axis shifts: out-of-bounds -> 0
        } else {
            hs = h; ws = w;         // diagonal shifts: border -> identity
        }
    }

    const int t0 = tchunk * 112 + t_local;
    // float4 index of (ns, m, t, c4): ((ns*12 + m)*784 + t)*16 + c4
    // max = 128*12*784*16 = 19,267,584 < 2^31  -> 32-bit offsets are safe.
    const int base_out = ((ns * 12 + m) * 784 + t0) * 16 + c4;

    float4 v[7];
#pragma unroll
    for (int i = 0; i < 7; i++) v[i] = make_float4(0.f, 0.f, 0.f, 0.f);

    if (!zero) {
        const int ns_src   = (ns & ~15) | (hs << 2) | ws;
        const int base_src = ((ns_src * 12 + m) * 784 + t0) * 16 + c4;
#pragma unroll
        for (int i = 0; i < 7; i++)
            v[i] = __ldg(x + base_src + i * 256);   // default cache: L2-resident
    }

#pragma unroll
    for (int i = 0; i < 7; i++)
        __stcs(out + base_out + i * 256, v[i]);
}

extern "C" void kernel_launch(void* const* d_in, const int* in_sizes, int n_in,
                              void* d_out, int out_size) {
    const float4* x = (const float4*)d_in[0];
    float4* out = (float4*)d_out;
    // blocks = 128 * 12 * 7 = 10,752 ; each moves 256 threads * 7 float4
    spatial_shift_kernel<<<10752, 256>>>(x, out);
}

// round 8
// speedup vs baseline: 1.0226x; 1.0032x over previous
#include <cuda_runtime.h>

// SpatialShift: x (ns=128, m=12, t=784, c=64) fp32.
// ns = b*16 + h*4 + w (H=W=4, shift s=1). Channel d = m*64 + c, fold f=48.
// Pure ns-index permutation => fully coalesced float4 streaming copy.
//
// R8: R4's 7-deep front-batch, but loads DEFAULT-cached (L2 keeps the ~24MB
// of duplicated diagonal-border reads for the second reader) and an inline-
// asm register pin between the load batch and store batch so ptxas cannot
// interleave them (R7 showed that without the pin, __ldg collapses the
// batch to depth ~4 / 28 regs). Stores remain streaming (__stcs).

// Packed delta tables: 2 bits per group g (0..8), value = delta + 1.
// dh: {+1,-1,0,0,-1,+1,-1,+1, 0}
// dw: { 0, 0,+1,-1,-1,+1,+1,-1, 0}
#define DH_PACK 100434u
#define DW_PACK 75813u

__global__ void __launch_bounds__(256)
spatial_shift_kernel(const float4* __restrict__ x, float4* __restrict__ out) {
    const int c4      = threadIdx.x & 15;   // float4 index within c (0..15)
    const int t_local = threadIdx.x >> 4;   // 0..15

    int blk = blockIdx.x;
    const int tchunk = blk % 7;   blk /= 7;    // 7 * 112 = 784 = t
    const int m      = blk % 12;  blk /= 12;
    const int ns     = blk;                    // 0..127

    const int h = (ns >> 2) & 3;
    const int w = ns & 3;

    const int d = m * 64 + c4 * 4;
    int g = d / 48;
    if (g > 8) g = 8;

    const int dh = (int)((DH_PACK >> (2 * g)) & 3u) - 1;
    const int dw = (int)((DW_PACK >> (2 * g)) & 3u) - 1;

    int hs = h + dh;
    int ws = w + dw;
    bool zero = false;
    if (((unsigned)hs > 3u) || ((unsigned)ws > 3u)) {
        if (g < 4) {
            zero = true;            // axis shifts: out-of-bounds -> 0
        } else {
            hs = h; ws = w;         // diagonal shifts: border -> identity
        }
    }

    const int t0 = tchunk * 112 + t_local;
    // float4 index of (ns, m, t, c4): ((ns*12 + m)*784 + t)*16 + c4
    // max = 128*12*784*16 = 19,267,584 < 2^31  -> 32-bit offsets are safe.
    const int base_out = ((ns * 12 + m) * 784 + t0) * 16 + c4;

    float4 v[7];
#pragma unroll
    for (int i = 0; i < 7; i++) v[i] = make_float4(0.f, 0.f, 0.f, 0.f);

    if (!zero) {
        const int ns_src   = (ns & ~15) | (hs << 2) | ws;
        const int base_src = ((ns_src * 12 + m) * 784 + t0) * 16 + c4;
#pragma unroll
        for (int i = 0; i < 7; i++)
            v[i] = __ldg(x + base_src + i * 256);   // default cache: L2 keeps dups

        // Pin all 28 floats live here: forces the full 7-deep LDG batch to
        // complete (and coexist in registers) before any store issues.
        asm volatile("" :
            "+f"(v[0].x), "+f"(v[0].y), "+f"(v[0].z), "+f"(v[0].w),
            "+f"(v[1].x), "+f"(v[1].y), "+f"(v[1].z), "+f"(v[1].w),
            "+f"(v[2].x), "+f"(v[2].y), "+f"(v[2].z), "+f"(v[2].w),
            "+f"(v[3].x), "+f"(v[3].y), "+f"(v[3].z), "+f"(v[3].w),
            "+f"(v[4].x), "+f"(v[4].y), "+f"(v[4].z), "+f"(v[4].w),
            "+f"(v[5].x), "+f"(v[5].y), "+f"(v[5].z), "+f"(v[5].w),
            "+f"(v[6].x), "+f"(v[6].y), "+f"(v[6].z), "+f"(v[6].w));
    }

#pragma unroll
    for (int i = 0; i < 7; i++)
        __stcs(out + base_out + i * 256, v[i]);
}

extern "C" void kernel_launch(void* const* d_in, const int* in_sizes, int n_in,
                              void* d_out, int out_size) {
    const float4* x = (const float4*)d_in[0];
    float4* out = (float4*)d_out;
    // blocks = 128 * 12 * 7 = 10,752 ; each moves 256 threads * 7 float4
    spatial_shift_kernel<<<10752, 256>>>(x, out);
}